// round 2
// baseline (speedup 1.0000x reference)
#include <cuda_runtime.h>
#include <math.h>

// EdgeModel: out[e] = softplus( concat(nf[src], nf[dst], ef[e], gf[batch[src]]) @ W.T ) - log(2)
// Shapes: nf [N,128], ef [E,64], gf [G,64], ei [2,E] int32, batch [N] int32, W [128,384]
// out [E,128] fp32.

#define BE 64      // edges per block
#define BK 32      // K-chunk
#define H  128     // hidden (output cols)
#define DN 128
#define DE 64
#define DG 64
#define NCHUNK 12  // 384 / 32
#define LOG2F_CONST 0.6931471805599453f

__global__ __launch_bounds__(256, 3)
void edge_mlp_kernel(const float* __restrict__ nf,
                     const float* __restrict__ ef,
                     const float* __restrict__ gf,
                     const int* __restrict__ ei,
                     const int* __restrict__ batch,
                     const float* __restrict__ W,
                     float* __restrict__ out,
                     int E)
{
    __shared__ float As[BK][BE];     // A tile, K-major (transposed)
    __shared__ float Ws[BK][H];      // W tile, K-major (transposed)
    __shared__ int s_src[BE], s_dst[BE], s_g[BE];

    const int tid = threadIdx.x;
    const int e0  = blockIdx.x * BE;

    // Load per-edge indices once (indices are int32 on device)
    if (tid < BE) {
        int e = e0 + tid;
        int s = 0, d = 0;
        if (e < E) { s = ei[e]; d = ei[E + e]; }
        s_src[tid] = s;
        s_dst[tid] = d;
        s_g[tid]   = batch[s];
    }
    __syncthreads();

    const int tx = tid & 15;   // 16 col-groups of 8
    const int ty = tid >> 4;   // 16 row-groups of 4

    float acc[4][8];
    #pragma unroll
    for (int i = 0; i < 4; ++i)
        #pragma unroll
        for (int j = 0; j < 8; ++j)
            acc[i][j] = 0.0f;

    for (int c = 0; c < NCHUNK; ++c) {
        // ---- Load A tile (gathered), 64 rows x 32 cols, transposed into As[k][e]
        // 512 float4 loads, 2 per thread. i -> (le = i/8, q = i%8), each float4 covers k=q*4..q*4+3
        #pragma unroll
        for (int r = 0; r < 2; ++r) {
            int i  = tid + 256 * r;
            int le = i >> 3;
            int q  = i & 7;
            int e  = e0 + le;
            float4 v = make_float4(0.f, 0.f, 0.f, 0.f);
            if (e < E) {
                const float* base;
                if (c < 4)       base = nf + (size_t)s_src[le] * DN + c * BK;
                else if (c < 8)  base = nf + (size_t)s_dst[le] * DN + (c - 4) * BK;
                else if (c < 10) base = ef + (size_t)e * DE + (c - 8) * BK;
                else             base = gf + (size_t)s_g[le] * DG + (c - 10) * BK;
                v = *(const float4*)(base + q * 4);
            }
            As[q * 4 + 0][le] = v.x;
            As[q * 4 + 1][le] = v.y;
            As[q * 4 + 2][le] = v.z;
            As[q * 4 + 3][le] = v.w;
        }
        // ---- Load W tile: 128 rows x 32 cols, transposed into Ws[k][o]
        // 1024 float4 loads, 4 per thread. i -> (o = i/8, q = i%8)
        #pragma unroll
        for (int r = 0; r < 4; ++r) {
            int i = tid + 256 * r;
            int o = i >> 3;
            int q = i & 7;
            float4 w = *(const float4*)(W + (size_t)o * 384 + c * BK + q * 4);
            Ws[q * 4 + 0][o] = w.x;
            Ws[q * 4 + 1][o] = w.y;
            Ws[q * 4 + 2][o] = w.z;
            Ws[q * 4 + 3][o] = w.w;
        }
        __syncthreads();

        // ---- 4x8 register-tile FFMA over the 32-deep K chunk
        #pragma unroll
        for (int k = 0; k < BK; ++k) {
            float4 a  = *(const float4*)(&As[k][ty * 4]);
            float4 b0 = *(const float4*)(&Ws[k][tx * 8]);
            float4 b1 = *(const float4*)(&Ws[k][tx * 8 + 4]);
            float av[4] = {a.x, a.y, a.z, a.w};
            float bv[8] = {b0.x, b0.y, b0.z, b0.w, b1.x, b1.y, b1.z, b1.w};
            #pragma unroll
            for (int i = 0; i < 4; ++i)
                #pragma unroll
                for (int j = 0; j < 8; ++j)
                    acc[i][j] = fmaf(av[i], bv[j], acc[i][j]);
        }
        __syncthreads();
    }

    // ---- Epilogue: shifted softplus, coalesced float4 stores
    #pragma unroll
    for (int i = 0; i < 4; ++i) {
        int e = e0 + ty * 4 + i;
        if (e >= E) continue;
        float r[8];
        #pragma unroll
        for (int j = 0; j < 8; ++j) {
            float h = acc[i][j];
            // numerically stable softplus: max(h,0) + log1p(exp(-|h|)) - log(2)
            r[j] = fmaxf(h, 0.0f) + log1pf(__expf(-fabsf(h))) - LOG2F_CONST;
        }
        float* po = out + (size_t)e * H + tx * 8;
        *(float4*)(po)     = make_float4(r[0], r[1], r[2], r[3]);
        *(float4*)(po + 4) = make_float4(r[4], r[5], r[6], r[7]);
    }
}

extern "C" void kernel_launch(void* const* d_in, const int* in_sizes, int n_in,
                              void* d_out, int out_size)
{
    const float* nf    = (const float*)d_in[0];
    const float* ef    = (const float*)d_in[1];
    const float* gf    = (const float*)d_in[2];
    const int*   ei    = (const int*)d_in[3];
    const int*   batch = (const int*)d_in[4];
    const float* W     = (const float*)d_in[5];
    float*       out   = (float*)d_out;

    int E = in_sizes[1] / DE;          // edge_feats is [E, 64]
    int grid = (E + BE - 1) / BE;
    edge_mlp_kernel<<<grid, 256>>>(nf, ef, gf, ei, batch, W, out, E);
}

// round 4
// speedup vs baseline: 3.8632x; 3.8632x over previous
#include <cuda_runtime.h>
#include <cuda_bf16.h>
#include <cstdint>
#include <math.h>

// ============================================================================
// EdgeModel via legacy HMMA (mma.sync, baseline PTX — tcgen05 unavailable in
// this harness's compute_103 PTX target):
//   out[e] = softplus( concat(nf[src], nf[dst], ef[e], gf[batch[src]]) @ W.T ) - log2
// Precision: fp32 -> bf16 hi/lo split; acc += Ahi*Whi + Ahi*Wlo + Alo*Whi (fp32).
// CTA tile: M=128 edges x N=128 out, K=384 in 6 chunks of 64.
// 256 threads = 8 warps, warp tile 32x64 (4 M-groups x 2 N-groups).
// ============================================================================

#define H        128
#define DN       128
#define DE       64
#define DG       64
#define KCHUNK   64
#define NCHUNKS  6
#define TILE_E   128
#define THREADS  256
#define LOG2F_CONST 0.6931471805599453f

#define SWZ128(off) ((off) ^ (((off) >> 3) & 0x70))

// smem layout (bytes): A rows/W rows are 64 bf16 = 128B, SW128-swizzled
#define SA_HI 0
#define SA_LO 16384
#define SW_HI 32768
#define SW_LO 49152
#define SIDX  65536
#define SMEM_TOTAL (SIDX + 3 * TILE_E * 4)   // 67072

// W image: [6 chunks][hi 16KB | lo 16KB], pre-swizzled SW128, rows = n (128B each)
__device__ uint4 g_Wimg[(NCHUNKS * 32768) / 16];

__global__ void w_convert_kernel(const float* __restrict__ W) {
    int i = blockIdx.x * 256 + threadIdx.x;          // over 6*128*64 = 49152
    if (i >= NCHUNKS * H * KCHUNK) return;
    int c   = i / (H * KCHUNK);
    int rem = i - c * (H * KCHUNK);
    int n   = rem >> 6;
    int kk  = rem & 63;
    float x = W[n * 384 + c * KCHUNK + kk];
    __nv_bfloat16 h = __float2bfloat16(x);
    __nv_bfloat16 l = __float2bfloat16(x - __bfloat162float(h));
    uint32_t off = SWZ128((uint32_t)(n * 128 + kk * 2));
    unsigned char* img = (unsigned char*)g_Wimg + c * 32768;
    *(__nv_bfloat16*)(img + off)         = h;
    *(__nv_bfloat16*)(img + 16384 + off) = l;
}

__device__ __forceinline__ uint32_t smem_u32(const void* p) {
    uint32_t a;
    asm("{ .reg .u64 t; cvta.to.shared.u64 t, %1; cvt.u32.u64 %0, t; }" : "=r"(a) : "l"(p));
    return a;
}

__device__ __forceinline__ void ldsm_x4(uint32_t* r, uint32_t addr) {
    asm volatile("ldmatrix.sync.aligned.m8n8.x4.shared.b16 {%0,%1,%2,%3}, [%4];"
                 : "=r"(r[0]), "=r"(r[1]), "=r"(r[2]), "=r"(r[3]) : "r"(addr));
}

__device__ __forceinline__ void mma_bf16(float* d, const uint32_t* a, uint32_t b0, uint32_t b1) {
    asm volatile(
        "mma.sync.aligned.m16n8k16.row.col.f32.bf16.bf16.f32 "
        "{%0,%1,%2,%3}, {%4,%5,%6,%7}, {%8,%9}, {%0,%1,%2,%3};"
        : "+f"(d[0]), "+f"(d[1]), "+f"(d[2]), "+f"(d[3])
        : "r"(a[0]), "r"(a[1]), "r"(a[2]), "r"(a[3]), "r"(b0), "r"(b1));
}

__device__ __forceinline__ float softplus_shift(float h) {
    return fmaxf(h, 0.0f) + __logf(1.0f + __expf(-fabsf(h))) - LOG2F_CONST;
}

__global__ __launch_bounds__(THREADS, 2)
void edge_hmma_kernel(const float* __restrict__ nf,
                      const float* __restrict__ ef,
                      const float* __restrict__ gf,
                      const int*   __restrict__ ei,
                      const int*   __restrict__ batch,
                      float*       __restrict__ out,
                      int E)
{
    extern __shared__ __align__(1024) char smem[];
    const uint32_t sbase = smem_u32(smem);
    const int tid  = threadIdx.x;
    const int wid  = tid >> 5;
    const int lane = tid & 31;
    const int e0   = blockIdx.x * TILE_E;

    int* s_src = (int*)(smem + SIDX);
    int* s_dst = s_src + TILE_E;
    int* s_g   = s_dst + TILE_E;
    if (tid < TILE_E) {
        int e = e0 + tid;
        int s = 0, d = 0, g = 0;
        if (e < E) { s = ei[e]; d = ei[E + e]; g = batch[s]; }
        s_src[tid] = s; s_dst[tid] = d; s_g[tid] = g;
    }
    __syncthreads();

    const int wm = wid & 3;        // M group of 32
    const int wn = wid >> 2;       // N group of 64

    float acc[2][8][4];
    #pragma unroll
    for (int g = 0; g < 2; ++g)
        #pragma unroll
        for (int n = 0; n < 8; ++n)
            #pragma unroll
            for (int k = 0; k < 4; ++k)
                acc[g][n][k] = 0.0f;

    // gather thread mapping: 2 threads per row, 32 floats each
    const int gr = tid >> 1;
    const int gq = tid & 1;

    for (int c = 0; c < NCHUNKS; ++c) {
        // ---- A gather + bf16 hi/lo split into swizzled smem ----
        {
            const int e  = e0 + gr;
            const int ec = (e < E) ? e : 0;
            const float* srcp;
            switch (c) {
                case 0:  srcp = nf + (size_t)s_src[gr] * DN;      break;
                case 1:  srcp = nf + (size_t)s_src[gr] * DN + 64; break;
                case 2:  srcp = nf + (size_t)s_dst[gr] * DN;      break;
                case 3:  srcp = nf + (size_t)s_dst[gr] * DN + 64; break;
                case 4:  srcp = ef + (size_t)ec * DE;             break;
                default: srcp = gf + (size_t)s_g[gr] * DG;        break;
            }
            #pragma unroll
            for (int j = 0; j < 8; ++j) {
                const int col = gq * 32 + j * 4;
                float4 v = *(const float4*)(srcp + col);
                __nv_bfloat162 h01 = __floats2bfloat162_rn(v.x, v.y);
                __nv_bfloat162 h23 = __floats2bfloat162_rn(v.z, v.w);
                float2 f01 = __bfloat1622float2(h01);
                float2 f23 = __bfloat1622float2(h23);
                __nv_bfloat162 l01 = __floats2bfloat162_rn(v.x - f01.x, v.y - f01.y);
                __nv_bfloat162 l23 = __floats2bfloat162_rn(v.z - f23.x, v.w - f23.y);
                uint2 hp, lp;
                hp.x = *(uint32_t*)&h01; hp.y = *(uint32_t*)&h23;
                lp.x = *(uint32_t*)&l01; lp.y = *(uint32_t*)&l23;
                const uint32_t sw = SWZ128((uint32_t)(gr * 128 + col * 2));
                *(uint2*)(smem + SA_HI + sw) = hp;
                *(uint2*)(smem + SA_LO + sw) = lp;
            }
        }
        // ---- W chunk copy (pre-swizzled hi+lo, 32KB contiguous) ----
        {
            const uint4* wsrc = g_Wimg + (size_t)c * 2048;
            uint4* wdst = (uint4*)(smem + SW_HI);
            #pragma unroll
            for (int i = 0; i < 8; ++i)
                wdst[tid + i * THREADS] = wsrc[tid + i * THREADS];
        }
        __syncthreads();

        // ---- compute: 4 k-steps of 16 ----
        #pragma unroll
        for (int ks = 0; ks < 4; ++ks) {
            uint32_t ah[2][4], al[2][4];
            const int arow  = wm * 32 + (lane & 15);
            const int akb   = ks * 32 + ((lane >> 4) & 1) * 16;
            #pragma unroll
            for (int g = 0; g < 2; ++g) {
                const uint32_t aoff = SWZ128((uint32_t)((arow + g * 16) * 128 + akb));
                ldsm_x4(ah[g], sbase + SA_HI + aoff);
                ldsm_x4(al[g], sbase + SA_LO + aoff);
            }
            const int brow = wn * 64 + (lane & 7) + ((lane >> 4) & 1) * 8;
            const int bkb  = ks * 32 + ((lane >> 3) & 1) * 16;
            #pragma unroll
            for (int ng = 0; ng < 4; ++ng) {
                uint32_t bh[4], bl[4];
                const uint32_t boff = SWZ128((uint32_t)((brow + ng * 16) * 128 + bkb));
                ldsm_x4(bh, sbase + SW_HI + boff);
                ldsm_x4(bl, sbase + SW_LO + boff);
                #pragma unroll
                for (int g = 0; g < 2; ++g) {
                    mma_bf16(acc[g][2 * ng + 0], ah[g], bh[0], bh[1]);
                    mma_bf16(acc[g][2 * ng + 0], ah[g], bl[0], bl[1]);
                    mma_bf16(acc[g][2 * ng + 0], al[g], bh[0], bh[1]);
                    mma_bf16(acc[g][2 * ng + 1], ah[g], bh[2], bh[3]);
                    mma_bf16(acc[g][2 * ng + 1], ah[g], bl[2], bl[3]);
                    mma_bf16(acc[g][2 * ng + 1], al[g], bh[2], bh[3]);
                }
            }
        }
        __syncthreads();
    }

    // ---- epilogue: softplus + store ----
    const int l4 = lane >> 2;
    const int l2 = (lane & 3) * 2;
    #pragma unroll
    for (int g = 0; g < 2; ++g) {
        const int r0 = e0 + wm * 32 + g * 16 + l4;
        const int r1 = r0 + 8;
        #pragma unroll
        for (int n8 = 0; n8 < 8; ++n8) {
            const int col = wn * 64 + n8 * 8 + l2;
            if (r0 < E) {
                float2 o;
                o.x = softplus_shift(acc[g][n8][0]);
                o.y = softplus_shift(acc[g][n8][1]);
                *(float2*)(out + (size_t)r0 * H + col) = o;
            }
            if (r1 < E) {
                float2 o;
                o.x = softplus_shift(acc[g][n8][2]);
                o.y = softplus_shift(acc[g][n8][3]);
                *(float2*)(out + (size_t)r1 * H + col) = o;
            }
        }
    }
}

extern "C" void kernel_launch(void* const* d_in, const int* in_sizes, int n_in,
                              void* d_out, int out_size)
{
    const float* nf    = (const float*)d_in[0];
    const float* ef    = (const float*)d_in[1];
    const float* gf    = (const float*)d_in[2];
    const int*   ei    = (const int*)d_in[3];
    const int*   batch = (const int*)d_in[4];
    const float* W     = (const float*)d_in[5];
    float*       out   = (float*)d_out;

    const int E = in_sizes[1] / DE;   // edge_feats is [E, 64]

    static bool attr_set = false;
    if (!attr_set) {
        cudaFuncSetAttribute(edge_hmma_kernel,
                             cudaFuncAttributeMaxDynamicSharedMemorySize, SMEM_TOTAL);
        attr_set = true;
    }

    w_convert_kernel<<<(NCHUNKS * H * KCHUNK + 255) / 256, 256>>>(W);
    const int grid = (E + TILE_E - 1) / TILE_E;
    edge_hmma_kernel<<<grid, THREADS, SMEM_TOTAL>>>(nf, ef, gf, ei, batch, out, E);
}

// round 5
// speedup vs baseline: 4.1710x; 1.0797x over previous
#include <cuda_runtime.h>
#include <cuda_bf16.h>
#include <cstdint>
#include <math.h>

// ============================================================================
// EdgeModel via tf32 mma.sync (baseline PTX; tcgen05 not available at the
// harness's compute_103 target):
//   out[e] = softplus( concat(nf[src], nf[dst], ef[e], gf[batch[src]]) @ W.T ) - log2
// Single-pass tf32 (both operands cvt.rna rounded), fp32 accumulate.
// CTA tile: 256 edges x 128 out; 8 warps, warp tile 64x64.
// K = 384 in 12 chunks of 32 fp32 (128B rows, SW128 swizzle).
// cp.async double-buffered gather; W pre-converted/pre-swizzled to global image.
// ============================================================================

#define H        128
#define DN       128
#define DE       64
#define DG       64
#define KC       32
#define NCH      12
#define TILE_E   256
#define THREADS  256
#define LOG2F_CONST 0.6931471805599453f

#define SWZ128(off) ((off) ^ (((off) >> 3) & 0x70))

// smem: per buffer: A 256x128B = 32KB, W 128x128B = 16KB
#define BUFSZ  49152
#define SIDX   (2 * BUFSZ)
#define SMEM_TOTAL (SIDX + 3 * TILE_E * 4)   // 101376

// W image: [12 chunks][128 n x 32 k fp32(tf32-rounded)], SW128-swizzled rows
__device__ uint32_t g_Wimg[NCH * 128 * KC];

__device__ __forceinline__ uint32_t f2tf32(float x) {
    uint32_t r; asm("cvt.rna.tf32.f32 %0, %1;" : "=r"(r) : "f"(x)); return r;
}

__global__ void w_convert_kernel(const float* __restrict__ W) {
    int i = blockIdx.x * 256 + threadIdx.x;     // over 128*384
    if (i >= H * 384) return;
    int n = i / 384;
    int k = i - n * 384;
    int c  = k >> 5;
    int kk = k & 31;
    uint32_t v = f2tf32(W[n * 384 + k]);
    unsigned char* img = (unsigned char*)g_Wimg + c * 16384;
    *(uint32_t*)(img + SWZ128((uint32_t)(n * 128 + kk * 4))) = v;
}

__device__ __forceinline__ uint32_t smem_u32(const void* p) {
    uint32_t a;
    asm("{ .reg .u64 t; cvta.to.shared.u64 t, %1; cvt.u32.u64 %0, t; }" : "=r"(a) : "l"(p));
    return a;
}
__device__ __forceinline__ void ldsm_x4(uint32_t* r, uint32_t addr) {
    asm volatile("ldmatrix.sync.aligned.m8n8.x4.shared.b16 {%0,%1,%2,%3}, [%4];"
                 : "=r"(r[0]), "=r"(r[1]), "=r"(r[2]), "=r"(r[3]) : "r"(addr));
}
__device__ __forceinline__ void cp_async16(uint32_t dst, const void* src) {
    asm volatile("cp.async.cg.shared.global [%0], [%1], 16;" :: "r"(dst), "l"(src));
}
__device__ __forceinline__ void mma_tf32(float* d, const uint32_t* a, uint32_t b0, uint32_t b1) {
    asm volatile(
        "mma.sync.aligned.m16n8k8.row.col.f32.tf32.tf32.f32 "
        "{%0,%1,%2,%3}, {%4,%5,%6,%7}, {%8,%9}, {%0,%1,%2,%3};"
        : "+f"(d[0]), "+f"(d[1]), "+f"(d[2]), "+f"(d[3])
        : "r"(a[0]), "r"(a[1]), "r"(a[2]), "r"(a[3]), "r"(b0), "r"(b1));
}
__device__ __forceinline__ float softplus_shift(float h) {
    return fmaxf(h, 0.0f) + __logf(1.0f + __expf(-fabsf(h))) - LOG2F_CONST;
}

__global__ __launch_bounds__(THREADS, 1)
void edge_tf32_kernel(const float* __restrict__ nf,
                      const float* __restrict__ ef,
                      const float* __restrict__ gf,
                      const int*   __restrict__ ei,
                      const int*   __restrict__ batch,
                      float*       __restrict__ out,
                      int E)
{
    extern __shared__ __align__(1024) char smem[];
    const uint32_t sbase = smem_u32(smem);
    const int tid  = threadIdx.x;
    const int wid  = tid >> 5;
    const int lane = tid & 31;
    const int e0   = blockIdx.x * TILE_E;

    int* s_src = (int*)(smem + SIDX);
    int* s_dst = s_src + TILE_E;
    int* s_g   = s_dst + TILE_E;
    {
        int e = e0 + tid;
        int s = 0, d = 0, g = 0;
        if (e < E) { s = ei[e]; d = ei[E + e]; g = batch[s]; }
        s_src[tid] = s; s_dst[tid] = d; s_g[tid] = g;
    }
    __syncthreads();

    const int wm = wid & 3;     // M group: rows wm*64
    const int wn = wid >> 2;    // N group: cols wn*64

    float acc[4][8][4];
    #pragma unroll
    for (int mt = 0; mt < 4; ++mt)
        #pragma unroll
        for (int nt = 0; nt < 8; ++nt)
            #pragma unroll
            for (int q = 0; q < 4; ++q)
                acc[mt][nt][q] = 0.0f;

    const int ecl = (e0 + tid < E) ? (e0 + tid) : 0;

    // ---- async producer: one chunk -> buffer b ----
    auto issue_chunk = [&](int c, int b) {
        const float* srcp;
        if (c < 4)       srcp = nf + (size_t)s_src[tid] * DN + c * KC;
        else if (c < 8)  srcp = nf + (size_t)s_dst[tid] * DN + (c - 4) * KC;
        else if (c < 10) srcp = ef + (size_t)ecl * DE + (c - 8) * KC;
        else             srcp = gf + (size_t)s_g[tid] * DG + (c - 10) * KC;
        const uint32_t abase = sbase + b * BUFSZ;
        #pragma unroll
        for (int j = 0; j < 8; ++j)
            cp_async16(abase + SWZ128((uint32_t)(tid * 128 + j * 16)), srcp + j * 4);
        const uint32_t wbase = sbase + b * BUFSZ + 32768;
        const char* wsrc = (const char*)g_Wimg + (size_t)c * 16384 + tid * 64;
        #pragma unroll
        for (int j = 0; j < 4; ++j)
            cp_async16(wbase + tid * 64 + j * 16, wsrc + j * 16);
        asm volatile("cp.async.commit_group;" ::: "memory");
    };

    issue_chunk(0, 0);

    for (int c = 0; c < NCH; ++c) {
        const int b = c & 1;
        if (c + 1 < NCH) {
            issue_chunk(c + 1, (c + 1) & 1);
            asm volatile("cp.async.wait_group 1;" ::: "memory");
        } else {
            asm volatile("cp.async.wait_group 0;" ::: "memory");
        }
        __syncthreads();

        const uint32_t Abase = sbase + b * BUFSZ;
        const uint32_t Bbase = Abase + 32768;

        // rounds of the K=32 chunk: 4 k-steps of 8
        #pragma unroll
        for (int ks = 0; ks < 4; ++ks) {
            uint32_t af[4][4], bf[4][4];
            // A fragments: tiles {m..m+7,k0-3},{m+8..,k0-3},{m..,k4-7},{m+8,k4-7}
            {
                const int rofs = ((lane >> 3) & 1) * 8 + (lane & 7);
                const int cofs = ks * 32 + ((lane >> 4) & 1) * 16;
                #pragma unroll
                for (int mt = 0; mt < 4; ++mt) {
                    const int row = wm * 64 + mt * 16 + rofs;
                    ldsm_x4(af[mt], Abase + SWZ128((uint32_t)(row * 128 + cofs)));
                }
            }
            // B fragments: tiles {n..n+7,k0-3},{n..n+7,k4-7},{n+8..,k0-3},{n+8,k4-7}
            {
                const int rofs = ((lane >> 4) & 1) * 8 + (lane & 7);
                const int cofs = ks * 32 + ((lane >> 3) & 1) * 16;
                #pragma unroll
                for (int nt = 0; nt < 4; ++nt) {
                    const int row = wn * 64 + nt * 16 + rofs;
                    ldsm_x4(bf[nt], Bbase + SWZ128((uint32_t)(row * 128 + cofs)));
                }
            }
            #pragma unroll
            for (int mt = 0; mt < 4; ++mt)
                #pragma unroll
                for (int nt = 0; nt < 4; ++nt) {
                    mma_tf32(acc[mt][2 * nt + 0], af[mt], bf[nt][0], bf[nt][1]);
                    mma_tf32(acc[mt][2 * nt + 1], af[mt], bf[nt][2], bf[nt][3]);
                }
        }
        __syncthreads();
    }

    // ---- epilogue: softplus + store ----
    #pragma unroll
    for (int mt = 0; mt < 4; ++mt) {
        const int r0 = e0 + wm * 64 + mt * 16 + (lane >> 2);
        const int r1 = r0 + 8;
        #pragma unroll
        for (int nt = 0; nt < 8; ++nt) {
            const int col = wn * 64 + nt * 8 + (lane & 3) * 2;
            if (r0 < E) {
                float2 o;
                o.x = softplus_shift(acc[mt][nt][0]);
                o.y = softplus_shift(acc[mt][nt][1]);
                *(float2*)(out + (size_t)r0 * H + col) = o;
            }
            if (r1 < E) {
                float2 o;
                o.x = softplus_shift(acc[mt][nt][2]);
                o.y = softplus_shift(acc[mt][nt][3]);
                *(float2*)(out + (size_t)r1 * H + col) = o;
            }
        }
    }
}

extern "C" void kernel_launch(void* const* d_in, const int* in_sizes, int n_in,
                              void* d_out, int out_size)
{
    const float* nf    = (const float*)d_in[0];
    const float* ef    = (const float*)d_in[1];
    const float* gf    = (const float*)d_in[2];
    const int*   ei    = (const int*)d_in[3];
    const int*   batch = (const int*)d_in[4];
    const float* W     = (const float*)d_in[5];
    float*       out   = (float*)d_out;

    const int E = in_sizes[1] / DE;   // edge_feats is [E, 64]

    static bool attr_set = false;
    if (!attr_set) {
        cudaFuncSetAttribute(edge_tf32_kernel,
                             cudaFuncAttributeMaxDynamicSharedMemorySize, SMEM_TOTAL);
        attr_set = true;
    }

    w_convert_kernel<<<(H * 384 + 255) / 256, 256>>>(W);
    const int grid = (E + TILE_E - 1) / TILE_E;
    edge_tf32_kernel<<<grid, THREADS, SMEM_TOTAL>>>(nf, ef, gf, ei, batch, out, E);
}